// round 2
// baseline (speedup 1.0000x reference)
#include <cuda_runtime.h>
#include <cstdint>
#include <cmath>

#define B_  32
#define T_  64
#define V_  50257
#define E_  256
#define H_  512
#define G4H (4*H_)      // 2048
#define M_  (B_*T_)     // 2048 rows, ordered (t,b)

// ---------------- scratch (no allocs allowed) ----------------
__device__ float g_hgates[B_*G4H];       // 256 KB
__device__ float g_xgates[(size_t)M_*G4H];  // 16 MB
__device__ float g_hs[(size_t)M_*H_];       // 4 MB
__device__ float g_hid[(size_t)M_*2*H_];    // 8 MB
__device__ int   g_tok[M_];

// ---------------- token shift: x_seq[b,t] = emb[captions[b, t==0?0:t-1]] ----
__global__ void tok_kernel(const int* __restrict__ captions) {
    int m = blockIdx.x * blockDim.x + threadIdx.x;
    if (m >= M_) return;
    int t = m / B_, b = m % B_;
    int s = (t == 0) ? 0 : (t - 1);
    g_tok[m] = captions[b * T_ + s];
}

// ---------------- h_gates[b,g] = features[b,:]·W_hh[g,:] + b_ih[g] + b_hh[g]
__global__ void hgates_kernel(const float* __restrict__ features,
                              const float* __restrict__ W_hh,
                              const float* __restrict__ b_ih,
                              const float* __restrict__ b_hh) {
    __shared__ float feat[H_];
    int b = blockIdx.y;
    int tid = threadIdx.x;
    for (int i = tid; i < H_; i += blockDim.x) feat[i] = features[b * H_ + i];
    __syncthreads();
    int g = blockIdx.x * blockDim.x + tid;
    const float* w = W_hh + (size_t)g * H_;
    float acc = 0.f;
    #pragma unroll 8
    for (int k = 0; k < H_; k += 4) {
        float4 wv = *(const float4*)(w + k);
        acc += wv.x * feat[k] + wv.y * feat[k + 1] + wv.z * feat[k + 2] + wv.w * feat[k + 3];
    }
    g_hgates[b * G4H + g] = acc + b_ih[g] + b_hh[g];
}

// ---------------- generic NT SGEMM: C[m,n] = A[m,:]·B[n,:] (+bias) ---------
// A: M x K row-major (optional row gather), B: N x K row-major.
// BM=BN=128, BK=8, 256 threads, 8x8 per thread.
// MODE 0: C[m*N+n].  MODE 1: logits scatter C[(b*T+t)*V + n], m=(t*B+b).
// M must be a multiple of 128 (true here: 2048). N is guarded.
template<int MODE>
__global__ void __launch_bounds__(256)
gemm_nt(const float* __restrict__ A, const int* __restrict__ a_rows, int lda,
        const float* __restrict__ Bm, int ldb,
        const float* __restrict__ bias,
        float* __restrict__ C, int N, int K)
{
    __shared__ float As[8][128 + 4];
    __shared__ float Bs[8][128 + 4];

    const int tid = threadIdx.x;
    const int bm = blockIdx.x * 128;
    const int bn = blockIdx.y * 128;
    const int lr = tid >> 1;          // 0..127 : tile row being loaded
    const int lc = (tid & 1) * 4;     // 0 or 4 : k offset
    const int tx = tid & 15;          // 0..15
    const int ty = tid >> 4;          // 0..15

    const int arow = bm + lr;
    const float* Ap = A + (size_t)(a_rows ? a_rows[arow] : arow) * lda + lc;
    const int brow = bn + lr;
    const bool bvalid = brow < N;
    const float* Bp = Bm + (size_t)(bvalid ? brow : 0) * ldb + lc;

    float acc[8][8];
    #pragma unroll
    for (int i = 0; i < 8; i++)
        #pragma unroll
        for (int j = 0; j < 8; j++) acc[i][j] = 0.f;

    for (int k0 = 0; k0 < K; k0 += 8) {
        float4 av = *(const float4*)(Ap + k0);
        float4 bv = bvalid ? *(const float4*)(Bp + k0) : make_float4(0.f, 0.f, 0.f, 0.f);
        __syncthreads();
        As[lc + 0][lr] = av.x; As[lc + 1][lr] = av.y;
        As[lc + 2][lr] = av.z; As[lc + 3][lr] = av.w;
        Bs[lc + 0][lr] = bv.x; Bs[lc + 1][lr] = bv.y;
        Bs[lc + 2][lr] = bv.z; Bs[lc + 3][lr] = bv.w;
        __syncthreads();
        #pragma unroll
        for (int k = 0; k < 8; k++) {
            float ra[8], rb[8];
            *(float4*)&ra[0] = *(const float4*)&As[k][ty * 8];
            *(float4*)&ra[4] = *(const float4*)&As[k][ty * 8 + 4];
            *(float4*)&rb[0] = *(const float4*)&Bs[k][tx * 8];
            *(float4*)&rb[4] = *(const float4*)&Bs[k][tx * 8 + 4];
            #pragma unroll
            for (int i = 0; i < 8; i++)
                #pragma unroll
                for (int j = 0; j < 8; j++)
                    acc[i][j] += ra[i] * rb[j];
        }
    }

    #pragma unroll
    for (int i = 0; i < 8; i++) {
        int m = bm + ty * 8 + i;
        #pragma unroll
        for (int j = 0; j < 8; j++) {
            int n = bn + tx * 8 + j;
            if (n < N) {
                float v = acc[i][j] + (bias ? bias[n] : 0.f);
                if (MODE == 0) {
                    C[(size_t)m * N + n] = v;
                } else {
                    int b = m % B_, t = m / B_;
                    C[((size_t)b * T_ + t) * (size_t)V_ + n] = v;
                }
            }
        }
    }
}

// ---------------- elementwise cell scan (recurrence only carries c) --------
__device__ __forceinline__ float sigmoidf_(float x) { return 1.f / (1.f + expf(-x)); }

__global__ void lstm_scan_kernel() {
    int id = blockIdx.x * blockDim.x + threadIdx.x;
    if (id >= B_ * H_) return;
    int b = id / H_, h = id % H_;
    float hgi = g_hgates[b * G4H + h];
    float hgf = g_hgates[b * G4H + H_ + h];
    float hgg = g_hgates[b * G4H + 2 * H_ + h];
    float hgo = g_hgates[b * G4H + 3 * H_ + h];
    float c = 0.f;
    for (int t = 0; t < T_; t++) {
        const float* xg = g_xgates + (size_t)(t * B_ + b) * G4H;
        float i_ = sigmoidf_(xg[h] + hgi);
        float f_ = sigmoidf_(xg[H_ + h] + hgf);
        float gg = tanhf(xg[2 * H_ + h] + hgg);
        float o_ = sigmoidf_(xg[3 * H_ + h] + hgo);
        c = f_ * c + i_ * gg;
        g_hs[(size_t)(t * B_ + b) * H_ + h] = o_ * tanhf(c);
    }
}

// ---------------- launch ----------------
extern "C" void kernel_launch(void* const* d_in, const int* in_sizes, int n_in,
                              void* d_out, int out_size) {
    const float* features = (const float*)d_in[0];
    const int*   captions = (const int*)d_in[1];
    const float* emb      = (const float*)d_in[2];
    const float* W_ih     = (const float*)d_in[3];
    const float* W_hh     = (const float*)d_in[4];
    const float* b_ih     = (const float*)d_in[5];
    const float* b_hh     = (const float*)d_in[6];
    const float* W1       = (const float*)d_in[7];
    const float* b1       = (const float*)d_in[8];
    const float* W2       = (const float*)d_in[9];
    const float* b2       = (const float*)d_in[10];
    float* out = (float*)d_out;

    float *xg, *hs, *hid;
    int* tok;
    cudaGetSymbolAddress((void**)&xg,  g_xgates);
    cudaGetSymbolAddress((void**)&hs,  g_hs);
    cudaGetSymbolAddress((void**)&hid, g_hid);
    cudaGetSymbolAddress((void**)&tok, g_tok);

    tok_kernel<<<(M_ + 255) / 256, 256>>>(captions);
    hgates_kernel<<<dim3(G4H / 256, B_), 256>>>(features, W_hh, b_ih, b_hh);
    // x_gates: (2048 x 2048, K=256) with embedding-row gather on A
    gemm_nt<0><<<dim3(M_ / 128, G4H / 128), 256>>>(emb, tok, E_, W_ih, E_, nullptr, xg, G4H, E_);
    lstm_scan_kernel<<<(B_ * H_ + 255) / 256, 256>>>();
    // hid: (2048 x 1024, K=512)
    gemm_nt<0><<<dim3(M_ / 128, (2 * H_) / 128), 256>>>(hs, nullptr, H_, W1, H_, b1, hid, 2 * H_, H_);
    // logits: (2048 x 50257, K=1024), scatter to (b,t,v)
    gemm_nt<1><<<dim3(M_ / 128, (V_ + 127) / 128), 256>>>(hid, nullptr, 2 * H_, W2, 2 * H_, b2, out, V_, 2 * H_);
}

// round 4
// speedup vs baseline: 1.6737x; 1.6737x over previous
#include <cuda_runtime.h>
#include <cuda_fp16.h>
#include <cstdint>
#include <cmath>

#define B_  32
#define T_  64
#define V_  50257
#define E_  256
#define H_  512
#define G4H (4*H_)      // 2048
#define M_  (B_*T_)     // 2048
#define K2  (2*H_)      // 1024

// ---------------- scratch (no allocs allowed) ----------------
__device__ float g_hgates[B_*G4H];
__device__ float g_xgates[(size_t)M_*G4H];
__device__ float g_hs[(size_t)M_*H_];
__device__ float g_hid[(size_t)M_*K2];
__device__ int   g_tok[M_];
__device__ __half g_Ah[(size_t)M_*K2];
__device__ __half g_Al[(size_t)M_*K2];
__device__ __half g_Bh[(size_t)V_*K2];
__device__ __half g_Bl[(size_t)V_*K2];

// ================= helpers =================
__device__ __forceinline__ uint32_t s2u(const void* p) {
    uint32_t a;
    asm("{ .reg .u64 t; cvta.to.shared.u64 t, %1; cvt.u32.u64 %0, t; }" : "=r"(a) : "l"(p));
    return a;
}
__device__ __forceinline__ void cp16(uint32_t dst, const void* src) {
    asm volatile("cp.async.cg.shared.global [%0], [%1], 16;\n" :: "r"(dst), "l"(src));
}
__device__ __forceinline__ uint32_t lds32(uint32_t addr) {
    uint32_t v; asm volatile("ld.shared.b32 %0, [%1];" : "=r"(v) : "r"(addr)); return v;
}
__device__ __forceinline__ void mma16816(float* c, const uint32_t* a, const uint32_t* b) {
    asm volatile(
        "mma.sync.aligned.m16n8k16.row.col.f32.f16.f16.f32 "
        "{%0,%1,%2,%3}, {%4,%5,%6,%7}, {%8,%9}, {%0,%1,%2,%3};"
        : "+f"(c[0]), "+f"(c[1]), "+f"(c[2]), "+f"(c[3])
        : "r"(a[0]), "r"(a[1]), "r"(a[2]), "r"(a[3]), "r"(b[0]), "r"(b[1]));
}

// ================= small kernels =================
__global__ void tok_kernel(const int* __restrict__ captions) {
    int m = blockIdx.x * blockDim.x + threadIdx.x;
    if (m >= M_) return;
    int t = m / B_, b = m % B_;
    int s = (t == 0) ? 0 : (t - 1);
    g_tok[m] = captions[b * T_ + s];
}

__global__ void hgates_kernel(const float* __restrict__ features,
                              const float* __restrict__ W_hh,
                              const float* __restrict__ b_ih,
                              const float* __restrict__ b_hh) {
    __shared__ float feat[H_];
    int b = blockIdx.y;
    int tid = threadIdx.x;
    for (int i = tid; i < H_; i += blockDim.x) feat[i] = features[b * H_ + i];
    __syncthreads();
    int g = blockIdx.x * blockDim.x + tid;
    const float* w = W_hh + (size_t)g * H_;
    float acc = 0.f;
    #pragma unroll 8
    for (int k = 0; k < H_; k += 4) {
        float4 wv = *(const float4*)(w + k);
        acc += wv.x * feat[k] + wv.y * feat[k + 1] + wv.z * feat[k + 2] + wv.w * feat[k + 3];
    }
    g_hgates[b * G4H + g] = acc + b_ih[g] + b_hh[g];
}

// split fp32 -> fp16 hi + fp16 residual
__global__ void split_kernel(const float* __restrict__ x,
                             __half* __restrict__ hi,
                             __half* __restrict__ lo, size_t n) {
    size_t i = ((size_t)blockIdx.x * blockDim.x + threadIdx.x) * 4;
    if (i >= n) return;
    float4 v = *(const float4*)(x + i);
    __half h0 = __float2half_rn(v.x);
    __half h1 = __float2half_rn(v.y);
    __half h2 = __float2half_rn(v.z);
    __half h3 = __float2half_rn(v.w);
    __half2 hh0; hh0.x = h0; hh0.y = h1;
    __half2 hh1; hh1.x = h2; hh1.y = h3;
    *(__half2*)(hi + i)     = hh0;
    *(__half2*)(hi + i + 2) = hh1;
    __half2 ll0, ll1;
    ll0.x = __float2half_rn(v.x - __half2float(h0));
    ll0.y = __float2half_rn(v.y - __half2float(h1));
    ll1.x = __float2half_rn(v.z - __half2float(h2));
    ll1.y = __float2half_rn(v.w - __half2float(h3));
    *(__half2*)(lo + i)     = ll0;
    *(__half2*)(lo + i + 2) = ll1;
}

// ---------------- SIMT NT SGEMM for the two small GEMMs ----------------
__global__ void __launch_bounds__(256)
gemm_nt(const float* __restrict__ A, const int* __restrict__ a_rows, int lda,
        const float* __restrict__ Bm, int ldb,
        const float* __restrict__ bias,
        float* __restrict__ C, int N, int K)
{
    __shared__ float As[8][128 + 4];
    __shared__ float Bs[8][128 + 4];
    const int tid = threadIdx.x;
    const int bm = blockIdx.x * 128;
    const int bn = blockIdx.y * 128;
    const int lr = tid >> 1;
    const int lc = (tid & 1) * 4;
    const int tx = tid & 15;
    const int ty = tid >> 4;
    const int arow = bm + lr;
    const float* Ap = A + (size_t)(a_rows ? a_rows[arow] : arow) * lda + lc;
    const int brow = bn + lr;
    const bool bvalid = brow < N;
    const float* Bp = Bm + (size_t)(bvalid ? brow : 0) * ldb + lc;

    float acc[8][8];
    #pragma unroll
    for (int i = 0; i < 8; i++)
        #pragma unroll
        for (int j = 0; j < 8; j++) acc[i][j] = 0.f;

    for (int k0 = 0; k0 < K; k0 += 8) {
        float4 av = *(const float4*)(Ap + k0);
        float4 bv = bvalid ? *(const float4*)(Bp + k0) : make_float4(0.f, 0.f, 0.f, 0.f);
        __syncthreads();
        As[lc + 0][lr] = av.x; As[lc + 1][lr] = av.y;
        As[lc + 2][lr] = av.z; As[lc + 3][lr] = av.w;
        Bs[lc + 0][lr] = bv.x; Bs[lc + 1][lr] = bv.y;
        Bs[lc + 2][lr] = bv.z; Bs[lc + 3][lr] = bv.w;
        __syncthreads();
        #pragma unroll
        for (int k = 0; k < 8; k++) {
            float ra[8], rb[8];
            *(float4*)&ra[0] = *(const float4*)&As[k][ty * 8];
            *(float4*)&ra[4] = *(const float4*)&As[k][ty * 8 + 4];
            *(float4*)&rb[0] = *(const float4*)&Bs[k][tx * 8];
            *(float4*)&rb[4] = *(const float4*)&Bs[k][tx * 8 + 4];
            #pragma unroll
            for (int i = 0; i < 8; i++)
                #pragma unroll
                for (int j = 0; j < 8; j++)
                    acc[i][j] += ra[i] * rb[j];
        }
    }
    #pragma unroll
    for (int i = 0; i < 8; i++) {
        int m = bm + ty * 8 + i;
        #pragma unroll
        for (int j = 0; j < 8; j++) {
            int n = bn + tx * 8 + j;
            if (n < N) C[(size_t)m * N + n] = acc[i][j] + (bias ? bias[n] : 0.f);
        }
    }
}

// ---------------- elementwise cell scan ----------------
__device__ __forceinline__ float sigmoidf_(float x) { return 1.f / (1.f + __expf(-x)); }

__global__ void lstm_scan_kernel() {
    int id = blockIdx.x * blockDim.x + threadIdx.x;
    if (id >= B_ * H_) return;
    int b = id / H_, h = id % H_;
    float hgi = g_hgates[b * G4H + h];
    float hgf = g_hgates[b * G4H + H_ + h];
    float hgg = g_hgates[b * G4H + 2 * H_ + h];
    float hgo = g_hgates[b * G4H + 3 * H_ + h];
    float c = 0.f;
    for (int t = 0; t < T_; t++) {
        const float* xg = g_xgates + (size_t)(t * B_ + b) * G4H;
        float i_ = sigmoidf_(xg[h] + hgi);
        float f_ = sigmoidf_(xg[H_ + h] + hgf);
        float gg = tanhf(xg[2 * H_ + h] + hgg);
        float o_ = sigmoidf_(xg[3 * H_ + h] + hgo);
        c = f_ * c + i_ * gg;
        g_hs[(size_t)(t * B_ + b) * H_ + h] = o_ * tanhf(c);
    }
}

// ================= HMMA logits GEMM =================
// out[(b*T+t)*V + n] = sum_k hid[m][k]*W2[n][k] + b2[n],  m = t*B + b
// fp16 3-term split: logical K=3072 over [Ah,Ah,Al] x [Bh,Bl,Bh].
// BM=BN=128, BK=32, 8 warps (2x4), warp tile 64x32, 4-stage cp.async.
#define KITERS 96          // 3072/32
#define NS     4
#define ROWB   80          // smem row stride bytes (32 halves used + pad) -> conflict-free
#define AST    (128*ROWB)  // 10240 B per operand tile
#define STAGE  (2*AST)     // 20480 B
#define SMEM_MMA (NS*STAGE) // 81920 B

__device__ __forceinline__ void load_stage_mma(uint32_t base, int tid, int bm, int bn, int ki) {
    const int k0 = ki * 32;
    const int term = k0 >> 10;
    const int koff = k0 & 1023;
    const __half* Asrc = (term == 2) ? g_Al : g_Ah;
    const __half* Bsrc = (term == 1) ? g_Bl : g_Bh;
    #pragma unroll
    for (int i = 0; i < 2; i++) {
        int t = tid + i * 256;
        int r = t >> 2, c = t & 3;
        cp16(base + r * ROWB + c * 16, Asrc + (size_t)(bm + r) * K2 + koff + c * 8);
    }
    #pragma unroll
    for (int i = 0; i < 2; i++) {
        int t = tid + i * 256;
        int r = t >> 2, c = t & 3;
        int row = bn + r; if (row >= V_) row = V_ - 1;
        cp16(base + AST + r * ROWB + c * 16, Bsrc + (size_t)row * K2 + koff + c * 8);
    }
    asm volatile("cp.async.commit_group;\n" ::: "memory");
}

__global__ void __launch_bounds__(256, 1)
logits_mma_kernel(const float* __restrict__ b2, float* __restrict__ out)
{
    extern __shared__ char smem[];
    const uint32_t sb = s2u(smem);
    const int tid = threadIdx.x;
    const int lane = tid & 31, wid = tid >> 5;
    const int mw = wid >> 2, nw = wid & 3;      // 2 x 4 warps
    const int g = lane >> 2, tg = lane & 3;
    const int bm = blockIdx.x * 128;
    const int bn = blockIdx.y * 128;

    float acc[4][4][4];
    #pragma unroll
    for (int i = 0; i < 4; i++)
        #pragma unroll
        for (int j = 0; j < 4; j++)
            #pragma unroll
            for (int q = 0; q < 4; q++) acc[i][j][q] = 0.f;

    // prologue: fill NS-1 stages
    #pragma unroll
    for (int s = 0; s < NS - 1; s++)
        load_stage_mma(sb + s * STAGE, tid, bm, bn, s);

    for (int ki = 0; ki < KITERS; ki++) {
        asm volatile("cp.async.wait_group %0;\n" :: "n"(NS - 2) : "memory");
        __syncthreads();

        int kn = ki + NS - 1;
        if (kn < KITERS) load_stage_mma(sb + (kn & (NS - 1)) * STAGE, tid, bm, bn, kn);
        else             asm volatile("cp.async.commit_group;\n" ::: "memory");

        const uint32_t Ab = sb + (ki & (NS - 1)) * STAGE;
        const uint32_t Bb = Ab + AST;
        #pragma unroll
        for (int kk = 0; kk < 32; kk += 16) {
            uint32_t a[4][4], b[4][2];
            #pragma unroll
            for (int mf = 0; mf < 4; mf++) {
                uint32_t base = Ab + (mw * 64 + mf * 16 + g) * ROWB + (kk + tg * 2) * 2;
                a[mf][0] = lds32(base);
                a[mf][1] = lds32(base + 8 * ROWB);
                a[mf][2] = lds32(base + 16);
                a[mf][3] = lds32(base + 8 * ROWB + 16);
            }
            #pragma unroll
            for (int nf = 0; nf < 4; nf++) {
                uint32_t base = Bb + (nw * 32 + nf * 8 + g) * ROWB + (kk + tg * 2) * 2;
                b[nf][0] = lds32(base);
                b[nf][1] = lds32(base + 16);
            }
            #pragma unroll
            for (int mf = 0; mf < 4; mf++)
                #pragma unroll
                for (int nf = 0; nf < 4; nf++)
                    mma16816(acc[mf][nf], a[mf], b[nf]);
        }
    }

    // epilogue: direct stores with (t,b)->(b,t) scatter + bias
    #pragma unroll
    for (int mf = 0; mf < 4; mf++) {
        int m0 = bm + mw * 64 + mf * 16 + g;
        int m1 = m0 + 8;
        size_t r0 = ((size_t)(m0 & 31) * T_ + (m0 >> 5)) * V_;
        size_t r1 = ((size_t)(m1 & 31) * T_ + (m1 >> 5)) * V_;
        #pragma unroll
        for (int nf = 0; nf < 4; nf++) {
            int n = bn + nw * 32 + nf * 8 + tg * 2;
            if (n < V_) {
                float bi0 = __ldg(b2 + n);
                out[r0 + n] = acc[mf][nf][0] + bi0;
                out[r1 + n] = acc[mf][nf][2] + bi0;
                if (n + 1 < V_) {
                    float bi1 = __ldg(b2 + n + 1);
                    out[r0 + n + 1] = acc[mf][nf][1] + bi1;
                    out[r1 + n + 1] = acc[mf][nf][3] + bi1;
                }
            }
        }
    }
}

// ================= launch =================
extern "C" void kernel_launch(void* const* d_in, const int* in_sizes, int n_in,
                              void* d_out, int out_size) {
    const float* features = (const float*)d_in[0];
    const int*   captions = (const int*)d_in[1];
    const float* emb      = (const float*)d_in[2];
    const float* W_ih     = (const float*)d_in[3];
    const float* W_hh     = (const float*)d_in[4];
    const float* b_ih     = (const float*)d_in[5];
    const float* b_hh     = (const float*)d_in[6];
    const float* W1       = (const float*)d_in[7];
    const float* b1       = (const float*)d_in[8];
    const float* W2       = (const float*)d_in[9];
    const float* b2       = (const float*)d_in[10];
    float* out = (float*)d_out;

    float *xg, *hs, *hid;
    int* tok;
    __half *Ah, *Al, *Bh, *Bl;
    cudaGetSymbolAddress((void**)&xg,  g_xgates);
    cudaGetSymbolAddress((void**)&hs,  g_hs);
    cudaGetSymbolAddress((void**)&hid, g_hid);
    cudaGetSymbolAddress((void**)&tok, g_tok);
    cudaGetSymbolAddress((void**)&Ah,  g_Ah);
    cudaGetSymbolAddress((void**)&Al,  g_Al);
    cudaGetSymbolAddress((void**)&Bh,  g_Bh);
    cudaGetSymbolAddress((void**)&Bl,  g_Bl);

    cudaFuncSetAttribute(logits_mma_kernel,
                         cudaFuncAttributeMaxDynamicSharedMemorySize, SMEM_MMA);

    // W2 split (biggest prelim, no deps on others)
    {
        size_t n = (size_t)V_ * K2;
        split_kernel<<<(unsigned)(n / 4 / 256), 256>>>(W2, Bh, Bl, n);
    }
    tok_kernel<<<(M_ + 255) / 256, 256>>>(captions);
    hgates_kernel<<<dim3(G4H / 256, B_), 256>>>(features, W_hh, b_ih, b_hh);
    gemm_nt<<<dim3(M_ / 128, G4H / 128), 256>>>(emb, tok, E_, W_ih, E_, nullptr, xg, G4H, E_);
    lstm_scan_kernel<<<128, 128>>>();
    gemm_nt<<<dim3(M_ / 128, (2 * H_) / 128), 256>>>(hs, nullptr, H_, W1, H_, b1, hid, 2 * H_, H_);
    {
        size_t n = (size_t)M_ * K2;
        split_kernel<<<(unsigned)(n / 4 / 256), 256>>>(hid, Ah, Al, n);
    }
    // logits: 16 m-tiles (fast axis, shares B in L2) x 393 n-tiles
    logits_mma_kernel<<<dim3(M_ / 128, (V_ + 127) / 128), 256, SMEM_MMA>>>(b2, out);
}